// round 1
// baseline (speedup 1.0000x reference)
#include <cuda_runtime.h>
#include <math.h>
#include <stdint.h>

// ---------------------------------------------------------------------------
// Problem constants (Qwen3.5 MoE GatedDeltaNet, T=4096)
// ---------------------------------------------------------------------------
#define T_TOKENS   4096
#define HIDDEN     2048
#define NUM_K_HEADS 16
#define NUM_V_HEADS 32
#define DK         128
#define DV         128
#define KEY_DIM    (NUM_K_HEADS * DK)          // 2048
#define VALUE_DIM  (NUM_V_HEADS * DV)          // 4096
#define QKV_DIM    (2 * KEY_DIM + VALUE_DIM)   // 8192
#define KCONV      4

// ---------------------------------------------------------------------------
// Scratch (device globals; no allocations allowed)
// ---------------------------------------------------------------------------
__device__ float g_mixed[(size_t)T_TOKENS * QKV_DIM];   // raw qkv projection
__device__ float g_x[(size_t)T_TOKENS * QKV_DIM];       // post conv+silu (+ q/k l2norm in place)
__device__ float g_z[(size_t)T_TOKENS * VALUE_DIM];     // gate projection
__device__ float g_braw[(size_t)T_TOKENS * NUM_V_HEADS];
__device__ float g_araw[(size_t)T_TOKENS * NUM_V_HEADS];
__device__ float g_beta[(size_t)T_TOKENS * NUM_V_HEADS];
__device__ float g_expg[(size_t)T_TOKENS * NUM_V_HEADS];
__device__ float g_o[(size_t)T_TOKENS * VALUE_DIM];     // attention output, then gated+normed y

// ---------------------------------------------------------------------------
// Generic SGEMM: C[M,N] = A[M,K] @ B[N,K]^T   (A, B row-major)
// 128x128 block tile, BK=16, 256 threads, 8x8 microtile.
// ---------------------------------------------------------------------------
#define BM 128
#define BN 128
#define BK 16

__global__ __launch_bounds__(256) void sgemm_nt(const float* __restrict__ A,
                                                const float* __restrict__ B,
                                                float* __restrict__ C,
                                                int M, int N, int K) {
    __shared__ float As[BK][BM + 4];
    __shared__ float Bs[BK][BN + 4];

    const int tid = threadIdx.x;
    const int bm  = blockIdx.y * BM;
    const int bn  = blockIdx.x * BN;
    const int tr  = tid >> 4;          // 0..15
    const int tc  = tid & 15;          // 0..15
    const int lr  = tid >> 2;          // 0..63 load row
    const int lk  = (tid & 3) * 4;     // 0,4,8,12

    float acc[8][8];
#pragma unroll
    for (int i = 0; i < 8; i++)
#pragma unroll
        for (int j = 0; j < 8; j++) acc[i][j] = 0.f;

    for (int k0 = 0; k0 < K; k0 += BK) {
#pragma unroll
        for (int i = 0; i < 2; i++) {
            int row = bm + lr + i * 64;
            float4 v = make_float4(0.f, 0.f, 0.f, 0.f);
            if (row < M) v = *reinterpret_cast<const float4*>(A + (size_t)row * K + k0 + lk);
            As[lk + 0][lr + i * 64] = v.x;
            As[lk + 1][lr + i * 64] = v.y;
            As[lk + 2][lr + i * 64] = v.z;
            As[lk + 3][lr + i * 64] = v.w;
        }
#pragma unroll
        for (int i = 0; i < 2; i++) {
            int row = bn + lr + i * 64;
            float4 v = make_float4(0.f, 0.f, 0.f, 0.f);
            if (row < N) v = *reinterpret_cast<const float4*>(B + (size_t)row * K + k0 + lk);
            Bs[lk + 0][lr + i * 64] = v.x;
            Bs[lk + 1][lr + i * 64] = v.y;
            Bs[lk + 2][lr + i * 64] = v.z;
            Bs[lk + 3][lr + i * 64] = v.w;
        }
        __syncthreads();

#pragma unroll
        for (int kk = 0; kk < BK; kk++) {
            float ra[8], rb[8];
            const float4* ap = reinterpret_cast<const float4*>(&As[kk][tr * 8]);
            const float4* bp = reinterpret_cast<const float4*>(&Bs[kk][tc * 8]);
            float4 a0 = ap[0], a1 = ap[1];
            float4 b0 = bp[0], b1 = bp[1];
            ra[0] = a0.x; ra[1] = a0.y; ra[2] = a0.z; ra[3] = a0.w;
            ra[4] = a1.x; ra[5] = a1.y; ra[6] = a1.z; ra[7] = a1.w;
            rb[0] = b0.x; rb[1] = b0.y; rb[2] = b0.z; rb[3] = b0.w;
            rb[4] = b1.x; rb[5] = b1.y; rb[6] = b1.z; rb[7] = b1.w;
#pragma unroll
            for (int i = 0; i < 8; i++)
#pragma unroll
                for (int j = 0; j < 8; j++) acc[i][j] += ra[i] * rb[j];
        }
        __syncthreads();
    }

#pragma unroll
    for (int i = 0; i < 8; i++) {
        int row = bm + tr * 8 + i;
        if (row >= M) continue;
#pragma unroll
        for (int j = 0; j < 8; j++) {
            int col = bn + tc * 8 + j;
            if (col < N) C[(size_t)row * N + col] = acc[i][j];
        }
    }
}

// ---------------------------------------------------------------------------
// Depthwise causal conv1d (K=4) + SiLU: g_x = silu(conv(g_mixed))
// ---------------------------------------------------------------------------
__device__ __forceinline__ float silu_f(float s) { return s / (1.f + expf(-s)); }

__global__ void conv_silu_kernel(const float* __restrict__ cw) {
    int c = blockIdx.x * blockDim.x + threadIdx.x;   // channel 0..QKV_DIM-1
    int t = blockIdx.y;
    if (c >= QKV_DIM) return;
    float w0 = cw[c * 4 + 0], w1 = cw[c * 4 + 1];
    float w2 = cw[c * 4 + 2], w3 = cw[c * 4 + 3];
    float s = g_mixed[(size_t)t * QKV_DIM + c] * w3;
    if (t >= 1) s += g_mixed[(size_t)(t - 1) * QKV_DIM + c] * w2;
    if (t >= 2) s += g_mixed[(size_t)(t - 2) * QKV_DIM + c] * w1;
    if (t >= 3) s += g_mixed[(size_t)(t - 3) * QKV_DIM + c] * w0;
    g_x[(size_t)t * QKV_DIM + c] = silu_f(s);
}

// ---------------------------------------------------------------------------
// beta = sigmoid(b);  expg = exp(-exp(A_log) * softplus(a + dt_bias))
// ---------------------------------------------------------------------------
__global__ void prep_ba_kernel(const float* __restrict__ dt_bias,
                               const float* __restrict__ A_log) {
    int idx = blockIdx.x * blockDim.x + threadIdx.x;
    if (idx >= T_TOKENS * NUM_V_HEADS) return;
    int h = idx & (NUM_V_HEADS - 1);
    float b = g_braw[idx];
    float a = g_araw[idx];
    g_beta[idx] = 1.f / (1.f + expf(-b));
    float xin = a + dt_bias[h];
    float sp  = (xin > 20.f) ? xin : log1pf(expf(xin));
    float g   = -expf(A_log[h]) * sp;
    g_expg[idx] = expf(g);
}

// ---------------------------------------------------------------------------
// In-place L2 normalization of q and k head vectors (per token, per k-head)
// x <- x * rsqrt(sum(x^2) + 1e-6)
// ---------------------------------------------------------------------------
__global__ __launch_bounds__(128) void l2norm_qk_kernel() {
    int t = blockIdx.x;
    int w = threadIdx.x >> 5;
    int l = threadIdx.x & 31;
    for (int hh = w; hh < NUM_K_HEADS; hh += 4) {
#pragma unroll
        for (int which = 0; which < 2; which++) {
            float* base = g_x + (size_t)t * QKV_DIM + which * KEY_DIM + hh * DK;
            float4 v = reinterpret_cast<float4*>(base)[l];
            float ss = v.x * v.x + v.y * v.y + v.z * v.z + v.w * v.w;
#pragma unroll
            for (int o = 16; o >= 1; o >>= 1) ss += __shfl_xor_sync(0xffffffffu, ss, o);
            float r = rsqrtf(ss + 1e-6f);
            v.x *= r; v.y *= r; v.z *= r; v.w *= r;
            reinterpret_cast<float4*>(base)[l] = v;
        }
    }
}

// ---------------------------------------------------------------------------
// Gated delta rule recurrence.
// Grid: 128 blocks = 32 heads x 4 dv-chunks. Block: 128 threads (4 warps).
// Thread (w, l): dv = chunk*32 + w*8 + (l>>2); owns dk range [(l&3)*32, +32).
// kv and o reduced over the 4-lane dk groups via shfl_xor.
// Double-buffered loads of k, q, v, exp(g), beta hide L2 latency.
// ---------------------------------------------------------------------------
struct StepIn {
    float4 kb[8];
    float4 qb[8];
    float v, eg, be;
};

__device__ __forceinline__ void rec_load(int t, int h, const float* qbase,
                                         const float* kbase, const float* vbase,
                                         StepIn& s) {
    const float4* kp = reinterpret_cast<const float4*>(kbase + (size_t)t * QKV_DIM);
    const float4* qp = reinterpret_cast<const float4*>(qbase + (size_t)t * QKV_DIM);
#pragma unroll
    for (int i = 0; i < 8; i++) s.kb[i] = kp[i];
#pragma unroll
    for (int i = 0; i < 8; i++) s.qb[i] = qp[i];
    s.v  = vbase[(size_t)t * QKV_DIM];
    s.eg = g_expg[t * NUM_V_HEADS + h];
    s.be = g_beta[t * NUM_V_HEADS + h];
}

__device__ __forceinline__ void rec_step(int t, int h, int dv, int kg,
                                         float (&S)[32], const StepIn& in) {
    const float scale = 0.0883883476483184405f;   // 128^-0.5
    float kv = 0.f;
#pragma unroll
    for (int i = 0; i < 8; i++) {
        float4 k4 = in.kb[i];
        S[4 * i + 0] *= in.eg; kv += k4.x * S[4 * i + 0];
        S[4 * i + 1] *= in.eg; kv += k4.y * S[4 * i + 1];
        S[4 * i + 2] *= in.eg; kv += k4.z * S[4 * i + 2];
        S[4 * i + 3] *= in.eg; kv += k4.w * S[4 * i + 3];
    }
    kv += __shfl_xor_sync(0xffffffffu, kv, 1);
    kv += __shfl_xor_sync(0xffffffffu, kv, 2);
    float delta = (in.v - kv) * in.be;
    float o = 0.f;
#pragma unroll
    for (int i = 0; i < 8; i++) {
        float4 k4 = in.kb[i];
        float4 q4 = in.qb[i];
        S[4 * i + 0] += k4.x * delta; o += q4.x * S[4 * i + 0];
        S[4 * i + 1] += k4.y * delta; o += q4.y * S[4 * i + 1];
        S[4 * i + 2] += k4.z * delta; o += q4.z * S[4 * i + 2];
        S[4 * i + 3] += k4.w * delta; o += q4.w * S[4 * i + 3];
    }
    o += __shfl_xor_sync(0xffffffffu, o, 1);
    o += __shfl_xor_sync(0xffffffffu, o, 2);
    if (kg == 0) g_o[(size_t)t * VALUE_DIM + h * DV + dv] = o * scale;
}

__global__ __launch_bounds__(128) void recurrence_kernel() {
    const int h     = blockIdx.x >> 2;
    const int chunk = blockIdx.x & 3;
    const int w     = threadIdx.x >> 5;
    const int l     = threadIdx.x & 31;
    const int dv    = chunk * 32 + w * 8 + (l >> 2);
    const int kg    = l & 3;
    const int koff  = kg * 32;
    const int kh    = h >> 1;   // rep = NUM_V_HEADS / NUM_K_HEADS = 2

    const float* qbase = g_x + kh * DK + koff;
    const float* kbase = g_x + KEY_DIM + kh * DK + koff;
    const float* vbase = g_x + 2 * KEY_DIM + h * DV + dv;

    float S[32];
#pragma unroll
    for (int i = 0; i < 32; i++) S[i] = 0.f;

    StepIn bufA, bufB;
    rec_load(0, h, qbase, kbase, vbase, bufA);

    for (int t = 0; t < T_TOKENS; t += 2) {
        rec_load(t + 1, h, qbase, kbase, vbase, bufB);
        rec_step(t, h, dv, kg, S, bufA);
        if (t + 2 < T_TOKENS) rec_load(t + 2, h, qbase, kbase, vbase, bufA);
        rec_step(t + 1, h, dv, kg, S, bufB);
    }
}

// ---------------------------------------------------------------------------
// Gated RMSNorm: y = (o * rsqrt(mean(o^2)+1e-6) * norm_w) * silu(z), in place in g_o
// ---------------------------------------------------------------------------
__global__ __launch_bounds__(128) void gated_norm_kernel(const float* __restrict__ norm_w) {
    int t = blockIdx.x;
    int w = threadIdx.x >> 5;
    int l = threadIdx.x & 31;
    float4 nw = reinterpret_cast<const float4*>(norm_w)[l];
    for (int h = w; h < NUM_V_HEADS; h += 4) {
        float* obase = g_o + (size_t)t * VALUE_DIM + h * DV;
        const float* zbase = g_z + (size_t)t * VALUE_DIM + h * DV;
        float4 o4 = reinterpret_cast<float4*>(obase)[l];
        float ss = o4.x * o4.x + o4.y * o4.y + o4.z * o4.z + o4.w * o4.w;
#pragma unroll
        for (int o = 16; o >= 1; o >>= 1) ss += __shfl_xor_sync(0xffffffffu, ss, o);
        float r = rsqrtf(ss * (1.f / DV) + 1e-6f);
        float4 z4 = reinterpret_cast<const float4*>(zbase)[l];
        float4 y;
        y.x = o4.x * r * nw.x * silu_f(z4.x);
        y.y = o4.y * r * nw.y * silu_f(z4.y);
        y.z = o4.z * r * nw.z * silu_f(z4.z);
        y.w = o4.w * r * nw.w * silu_f(z4.w);
        reinterpret_cast<float4*>(obase)[l] = y;
    }
}

// ---------------------------------------------------------------------------
// Launch
// ---------------------------------------------------------------------------
extern "C" void kernel_launch(void* const* d_in, const int* in_sizes, int n_in,
                              void* d_out, int out_size) {
    const float* H     = (const float*)d_in[0];
    const float* Wqkv  = (const float*)d_in[1];
    const float* Wz    = (const float*)d_in[2];
    const float* Wb    = (const float*)d_in[3];
    const float* Wa    = (const float*)d_in[4];
    const float* convw = (const float*)d_in[5];
    const float* dtb   = (const float*)d_in[6];
    const float* Alog  = (const float*)d_in[7];
    const float* normw = (const float*)d_in[8];
    const float* Wout  = (const float*)d_in[9];
    float* out = (float*)d_out;

    float *mixed, *x, *z, *braw, *araw, *o;
    cudaGetSymbolAddress((void**)&mixed, g_mixed);
    cudaGetSymbolAddress((void**)&x,     g_x);
    cudaGetSymbolAddress((void**)&z,     g_z);
    cudaGetSymbolAddress((void**)&braw,  g_braw);
    cudaGetSymbolAddress((void**)&araw,  g_araw);
    cudaGetSymbolAddress((void**)&o,     g_o);
    (void)x;

    // Projections
    sgemm_nt<<<dim3(QKV_DIM / BN, T_TOKENS / BM), 256>>>(H, Wqkv, mixed, T_TOKENS, QKV_DIM, HIDDEN);
    sgemm_nt<<<dim3(VALUE_DIM / BN, T_TOKENS / BM), 256>>>(H, Wz, z, T_TOKENS, VALUE_DIM, HIDDEN);
    sgemm_nt<<<dim3(1, T_TOKENS / BM), 256>>>(H, Wb, braw, T_TOKENS, NUM_V_HEADS, HIDDEN);
    sgemm_nt<<<dim3(1, T_TOKENS / BM), 256>>>(H, Wa, araw, T_TOKENS, NUM_V_HEADS, HIDDEN);

    // Conv + SiLU
    conv_silu_kernel<<<dim3(QKV_DIM / 256, T_TOKENS), 256>>>(convw);

    // beta / exp(g)
    prep_ba_kernel<<<(T_TOKENS * NUM_V_HEADS + 255) / 256, 256>>>(dtb, Alog);

    // l2 norm of q,k (in place)
    l2norm_qk_kernel<<<T_TOKENS, 128>>>();

    // Gated delta rule recurrence
    recurrence_kernel<<<NUM_V_HEADS * 4, 128>>>();

    // Gated RMSNorm (in place into g_o)
    gated_norm_kernel<<<T_TOKENS, 128>>>(normw);

    // Output projection
    sgemm_nt<<<dim3(HIDDEN / BN, T_TOKENS / BM), 256>>>(o, Wout, out, T_TOKENS, HIDDEN, VALUE_DIM);
}

// round 2
// speedup vs baseline: 1.6777x; 1.6777x over previous
#include <cuda_runtime.h>
#include <cuda_bf16.h>
#include <math.h>
#include <stdint.h>

// ---------------------------------------------------------------------------
// Problem constants (Qwen3.5 MoE GatedDeltaNet, T=4096)
// ---------------------------------------------------------------------------
#define T_TOKENS   4096
#define HIDDEN     2048
#define NUM_K_HEADS 16
#define NUM_V_HEADS 32
#define DK         128
#define DV         128
#define KEY_DIM    (NUM_K_HEADS * DK)          // 2048
#define VALUE_DIM  (NUM_V_HEADS * DV)          // 4096
#define QKV_DIM    (2 * KEY_DIM + VALUE_DIM)   // 8192
#define KCONV      4

// ---------------------------------------------------------------------------
// Scratch (device globals; no allocations allowed)
// ---------------------------------------------------------------------------
__device__ float g_mixed[(size_t)T_TOKENS * QKV_DIM];   // raw qkv projection
__device__ float g_x[(size_t)T_TOKENS * QKV_DIM];       // post conv+silu (+ q/k l2norm in place)
__device__ float g_z[(size_t)T_TOKENS * VALUE_DIM];     // gate projection
__device__ float g_braw[(size_t)T_TOKENS * NUM_V_HEADS];
__device__ float g_araw[(size_t)T_TOKENS * NUM_V_HEADS];
__device__ float g_beta[(size_t)T_TOKENS * NUM_V_HEADS];
__device__ float g_expg[(size_t)T_TOKENS * NUM_V_HEADS];
__device__ float g_o[(size_t)T_TOKENS * VALUE_DIM];     // attention output, then gated+normed y

// ---------------------------------------------------------------------------
// Tensor-core GEMM with bf16 split (fp32-accurate): C[M,N] = A[M,K] @ B[N,K]^T
// Each fp32 input x is split x = hi + lo (bf16 each); product uses 3 MMAs:
// hi*hi + hi*lo + lo*hi  (error ~2^-16 relative).
// CTA tile 128x128, BK=32, 256 threads = 8 warps in 2(M) x 4(N), warp tile 64x32.
// Requires M % 128 == 0, K % 32 == 0 (true for all call sites). N guarded.
// ---------------------------------------------------------------------------
#define BM 128
#define BN 128
#define BKT 32
#define ASTR 40   // smem row stride in bf16 elems (80B -> conflict-free ldmatrix)
#define BSTR 40

__device__ __forceinline__ void mma16816(float* c, const uint32_t* a, const uint32_t* b) {
    asm volatile(
        "mma.sync.aligned.m16n8k16.row.col.f32.bf16.bf16.f32 "
        "{%0,%1,%2,%3}, {%4,%5,%6,%7}, {%8,%9}, {%0,%1,%2,%3};"
        : "+f"(c[0]), "+f"(c[1]), "+f"(c[2]), "+f"(c[3])
        : "r"(a[0]), "r"(a[1]), "r"(a[2]), "r"(a[3]), "r"(b[0]), "r"(b[1]));
}

#define LDSM4(R, addr)                                                        \
    asm volatile("ldmatrix.sync.aligned.m8n8.x4.shared.b16 {%0,%1,%2,%3}, [%4];" \
                 : "=r"((R)[0]), "=r"((R)[1]), "=r"((R)[2]), "=r"((R)[3])      \
                 : "r"(addr))
#define LDSM2(R, addr)                                                        \
    asm volatile("ldmatrix.sync.aligned.m8n8.x2.shared.b16 {%0,%1}, [%2];"     \
                 : "=r"((R)[0]), "=r"((R)[1])                                  \
                 : "r"(addr))

__device__ __forceinline__ void split4(float4 v, uint2& H, uint2& L) {
    __nv_bfloat16 hx = __float2bfloat16_rn(v.x);
    __nv_bfloat16 hy = __float2bfloat16_rn(v.y);
    __nv_bfloat16 hz = __float2bfloat16_rn(v.z);
    __nv_bfloat16 hw = __float2bfloat16_rn(v.w);
    __nv_bfloat162 h01; h01.x = hx; h01.y = hy;
    __nv_bfloat162 h23; h23.x = hz; h23.y = hw;
    H.x = *reinterpret_cast<uint32_t*>(&h01);
    H.y = *reinterpret_cast<uint32_t*>(&h23);
    float lx = v.x - __bfloat162float(hx);
    float ly = v.y - __bfloat162float(hy);
    float lz = v.z - __bfloat162float(hz);
    float lw = v.w - __bfloat162float(hw);
    __nv_bfloat162 l01; l01.x = __float2bfloat16_rn(lx); l01.y = __float2bfloat16_rn(ly);
    __nv_bfloat162 l23; l23.x = __float2bfloat16_rn(lz); l23.y = __float2bfloat16_rn(lw);
    L.x = *reinterpret_cast<uint32_t*>(&l01);
    L.y = *reinterpret_cast<uint32_t*>(&l23);
}

__global__ __launch_bounds__(256) void mma_gemm_nt(const float* __restrict__ A,
                                                   const float* __restrict__ B,
                                                   float* __restrict__ C,
                                                   int M, int N, int K) {
    __shared__ __nv_bfloat16 As_hi[BM * ASTR];
    __shared__ __nv_bfloat16 As_lo[BM * ASTR];
    __shared__ __nv_bfloat16 Bs_hi[BN * BSTR];
    __shared__ __nv_bfloat16 Bs_lo[BN * BSTR];

    const int tid  = threadIdx.x;
    const int lane = tid & 31;
    const int warp = tid >> 5;
    const int wm   = warp & 1;   // 0..1  (M 64-half)
    const int wn   = warp >> 1;  // 0..3  (N 32-quarter)
    const int bm   = blockIdx.y * BM;
    const int bn   = blockIdx.x * BN;

    const uint32_t sAhi = (uint32_t)__cvta_generic_to_shared(As_hi);
    const uint32_t sAlo = (uint32_t)__cvta_generic_to_shared(As_lo);
    const uint32_t sBhi = (uint32_t)__cvta_generic_to_shared(Bs_hi);
    const uint32_t sBlo = (uint32_t)__cvta_generic_to_shared(Bs_lo);

    float acc[4][4][4];
#pragma unroll
    for (int i = 0; i < 4; i++)
#pragma unroll
        for (int j = 0; j < 4; j++)
#pragma unroll
            for (int r = 0; r < 4; r++) acc[i][j][r] = 0.f;

    float4 aR[4], bR[4];

    auto loadG = [&](int k0) {
#pragma unroll
        for (int i = 0; i < 4; i++) {
            int idx = tid + i * 256;
            int r = idx >> 3, kc = idx & 7;
            aR[i] = *reinterpret_cast<const float4*>(A + (size_t)(bm + r) * K + k0 + kc * 4);
            if (bn + r < N)
                bR[i] = *reinterpret_cast<const float4*>(B + (size_t)(bn + r) * K + k0 + kc * 4);
            else
                bR[i] = make_float4(0.f, 0.f, 0.f, 0.f);
        }
    };

    auto storeS = [&]() {
#pragma unroll
        for (int i = 0; i < 4; i++) {
            int idx = tid + i * 256;
            int r = idx >> 3, kc = idx & 7;
            uint2 H, L;
            split4(aR[i], H, L);
            *reinterpret_cast<uint2*>(&As_hi[r * ASTR + kc * 4]) = H;
            *reinterpret_cast<uint2*>(&As_lo[r * ASTR + kc * 4]) = L;
            split4(bR[i], H, L);
            *reinterpret_cast<uint2*>(&Bs_hi[r * BSTR + kc * 4]) = H;
            *reinterpret_cast<uint2*>(&Bs_lo[r * BSTR + kc * 4]) = L;
        }
    };

    auto compute = [&]() {
#pragma unroll
        for (int kf = 0; kf < 2; kf++) {
            uint32_t ah[4][4], al[4][4], bh[4][2], bl[4][2];
            const uint32_t aoff =
                2u * ((wm * 64 + (lane & 15)) * ASTR + kf * 16 + (lane >> 4) * 8);
#pragma unroll
            for (int mi = 0; mi < 4; mi++) {
                uint32_t d = aoff + 2u * (mi * 16) * ASTR;
                LDSM4(ah[mi], sAhi + d);
                LDSM4(al[mi], sAlo + d);
            }
            const uint32_t boff =
                2u * ((wn * 32 + (lane & 7)) * BSTR + kf * 16 + ((lane >> 3) & 1) * 8);
#pragma unroll
            for (int ni = 0; ni < 4; ni++) {
                uint32_t d = boff + 2u * (ni * 8) * BSTR;
                LDSM2(bh[ni], sBhi + d);
                LDSM2(bl[ni], sBlo + d);
            }
#pragma unroll
            for (int mi = 0; mi < 4; mi++)
#pragma unroll
                for (int ni = 0; ni < 4; ni++) {
                    mma16816(acc[mi][ni], ah[mi], bh[ni]);
                    mma16816(acc[mi][ni], ah[mi], bl[ni]);
                    mma16816(acc[mi][ni], al[mi], bh[ni]);
                }
        }
    };

    const int ntile = K / BKT;
    loadG(0);
    storeS();
    __syncthreads();
    for (int it = 0; it < ntile; ++it) {
        if (it + 1 < ntile) loadG((it + 1) * BKT);
        compute();
        __syncthreads();
        if (it + 1 < ntile) {
            storeS();
            __syncthreads();
        }
    }

    // Epilogue: fragment layout c0:(r,c) c1:(r,c+1) c2:(r+8,c) c3:(r+8,c+1)
#pragma unroll
    for (int mi = 0; mi < 4; mi++) {
        int row0 = bm + wm * 64 + mi * 16 + (lane >> 2);
#pragma unroll
        for (int ni = 0; ni < 4; ni++) {
            int col = bn + wn * 32 + ni * 8 + (lane & 3) * 2;
            if (col < N) {
                *reinterpret_cast<float2*>(&C[(size_t)row0 * N + col]) =
                    make_float2(acc[mi][ni][0], acc[mi][ni][1]);
                *reinterpret_cast<float2*>(&C[(size_t)(row0 + 8) * N + col]) =
                    make_float2(acc[mi][ni][2], acc[mi][ni][3]);
            }
        }
    }
}

// ---------------------------------------------------------------------------
// Depthwise causal conv1d (K=4) + SiLU: g_x = silu(conv(g_mixed))
// ---------------------------------------------------------------------------
__device__ __forceinline__ float silu_f(float s) { return s / (1.f + expf(-s)); }

__global__ void conv_silu_kernel(const float* __restrict__ cw) {
    int c = blockIdx.x * blockDim.x + threadIdx.x;   // channel 0..QKV_DIM-1
    int t = blockIdx.y;
    if (c >= QKV_DIM) return;
    float w0 = cw[c * 4 + 0], w1 = cw[c * 4 + 1];
    float w2 = cw[c * 4 + 2], w3 = cw[c * 4 + 3];
    float s = g_mixed[(size_t)t * QKV_DIM + c] * w3;
    if (t >= 1) s += g_mixed[(size_t)(t - 1) * QKV_DIM + c] * w2;
    if (t >= 2) s += g_mixed[(size_t)(t - 2) * QKV_DIM + c] * w1;
    if (t >= 3) s += g_mixed[(size_t)(t - 3) * QKV_DIM + c] * w0;
    g_x[(size_t)t * QKV_DIM + c] = silu_f(s);
}

// ---------------------------------------------------------------------------
// beta = sigmoid(b);  expg = exp(-exp(A_log) * softplus(a + dt_bias))
// ---------------------------------------------------------------------------
__global__ void prep_ba_kernel(const float* __restrict__ dt_bias,
                               const float* __restrict__ A_log) {
    int idx = blockIdx.x * blockDim.x + threadIdx.x;
    if (idx >= T_TOKENS * NUM_V_HEADS) return;
    int h = idx & (NUM_V_HEADS - 1);
    float b = g_braw[idx];
    float a = g_araw[idx];
    g_beta[idx] = 1.f / (1.f + expf(-b));
    float xin = a + dt_bias[h];
    float sp  = (xin > 20.f) ? xin : log1pf(expf(xin));
    float g   = -expf(A_log[h]) * sp;
    g_expg[idx] = expf(g);
}

// ---------------------------------------------------------------------------
// In-place L2 normalization of q and k head vectors (per token, per k-head)
// ---------------------------------------------------------------------------
__global__ __launch_bounds__(128) void l2norm_qk_kernel() {
    int t = blockIdx.x;
    int w = threadIdx.x >> 5;
    int l = threadIdx.x & 31;
    for (int hh = w; hh < NUM_K_HEADS; hh += 4) {
#pragma unroll
        for (int which = 0; which < 2; which++) {
            float* base = g_x + (size_t)t * QKV_DIM + which * KEY_DIM + hh * DK;
            float4 v = reinterpret_cast<float4*>(base)[l];
            float ss = v.x * v.x + v.y * v.y + v.z * v.z + v.w * v.w;
#pragma unroll
            for (int o = 16; o >= 1; o >>= 1) ss += __shfl_xor_sync(0xffffffffu, ss, o);
            float r = rsqrtf(ss + 1e-6f);
            v.x *= r; v.y *= r; v.z *= r; v.w *= r;
            reinterpret_cast<float4*>(base)[l] = v;
        }
    }
}

// ---------------------------------------------------------------------------
// Gated delta rule recurrence.
// Grid: 128 blocks = 32 heads x 4 dv-chunks. Block: 128 threads (4 warps).
// ---------------------------------------------------------------------------
struct StepIn {
    float4 kb[8];
    float4 qb[8];
    float v, eg, be;
};

__device__ __forceinline__ void rec_load(int t, int h, const float* qbase,
                                         const float* kbase, const float* vbase,
                                         StepIn& s) {
    const float4* kp = reinterpret_cast<const float4*>(kbase + (size_t)t * QKV_DIM);
    const float4* qp = reinterpret_cast<const float4*>(qbase + (size_t)t * QKV_DIM);
#pragma unroll
    for (int i = 0; i < 8; i++) s.kb[i] = kp[i];
#pragma unroll
    for (int i = 0; i < 8; i++) s.qb[i] = qp[i];
    s.v  = vbase[(size_t)t * QKV_DIM];
    s.eg = g_expg[t * NUM_V_HEADS + h];
    s.be = g_beta[t * NUM_V_HEADS + h];
}

__device__ __forceinline__ void rec_step(int t, int h, int dv, int kg,
                                         float (&S)[32], const StepIn& in) {
    const float scale = 0.0883883476483184405f;   // 128^-0.5
    float kv = 0.f;
#pragma unroll
    for (int i = 0; i < 8; i++) {
        float4 k4 = in.kb[i];
        S[4 * i + 0] *= in.eg; kv += k4.x * S[4 * i + 0];
        S[4 * i + 1] *= in.eg; kv += k4.y * S[4 * i + 1];
        S[4 * i + 2] *= in.eg; kv += k4.z * S[4 * i + 2];
        S[4 * i + 3] *= in.eg; kv += k4.w * S[4 * i + 3];
    }
    kv += __shfl_xor_sync(0xffffffffu, kv, 1);
    kv += __shfl_xor_sync(0xffffffffu, kv, 2);
    float delta = (in.v - kv) * in.be;
    float o = 0.f;
#pragma unroll
    for (int i = 0; i < 8; i++) {
        float4 k4 = in.kb[i];
        float4 q4 = in.qb[i];
        S[4 * i + 0] += k4.x * delta; o += q4.x * S[4 * i + 0];
        S[4 * i + 1] += k4.y * delta; o += q4.y * S[4 * i + 1];
        S[4 * i + 2] += k4.z * delta; o += q4.z * S[4 * i + 2];
        S[4 * i + 3] += k4.w * delta; o += q4.w * S[4 * i + 3];
    }
    o += __shfl_xor_sync(0xffffffffu, o, 1);
    o += __shfl_xor_sync(0xffffffffu, o, 2);
    if (kg == 0) g_o[(size_t)t * VALUE_DIM + h * DV + dv] = o * scale;
}

__global__ __launch_bounds__(128) void recurrence_kernel() {
    const int h     = blockIdx.x >> 2;
    const int chunk = blockIdx.x & 3;
    const int w     = threadIdx.x >> 5;
    const int l     = threadIdx.x & 31;
    const int dv    = chunk * 32 + w * 8 + (l >> 2);
    const int kg    = l & 3;
    const int koff  = kg * 32;
    const int kh    = h >> 1;   // rep = 2

    const float* qbase = g_x + kh * DK + koff;
    const float* kbase = g_x + KEY_DIM + kh * DK + koff;
    const float* vbase = g_x + 2 * KEY_DIM + h * DV + dv;

    float S[32];
#pragma unroll
    for (int i = 0; i < 32; i++) S[i] = 0.f;

    StepIn bufA, bufB;
    rec_load(0, h, qbase, kbase, vbase, bufA);

    for (int t = 0; t < T_TOKENS; t += 2) {
        rec_load(t + 1, h, qbase, kbase, vbase, bufB);
        rec_step(t, h, dv, kg, S, bufA);
        if (t + 2 < T_TOKENS) rec_load(t + 2, h, qbase, kbase, vbase, bufA);
        rec_step(t + 1, h, dv, kg, S, bufB);
    }
}

// ---------------------------------------------------------------------------
// Gated RMSNorm: y = (o * rsqrt(mean(o^2)+1e-6) * norm_w) * silu(z)
// ---------------------------------------------------------------------------
__global__ __launch_bounds__(128) void gated_norm_kernel(const float* __restrict__ norm_w) {
    int t = blockIdx.x;
    int w = threadIdx.x >> 5;
    int l = threadIdx.x & 31;
    float4 nw = reinterpret_cast<const float4*>(norm_w)[l];
    for (int h = w; h < NUM_V_HEADS; h += 4) {
        float* obase = g_o + (size_t)t * VALUE_DIM + h * DV;
        const float* zbase = g_z + (size_t)t * VALUE_DIM + h * DV;
        float4 o4 = reinterpret_cast<float4*>(obase)[l];
        float ss = o4.x * o4.x + o4.y * o4.y + o4.z * o4.z + o4.w * o4.w;
#pragma unroll
        for (int o = 16; o >= 1; o >>= 1) ss += __shfl_xor_sync(0xffffffffu, ss, o);
        float r = rsqrtf(ss * (1.f / DV) + 1e-6f);
        float4 z4 = reinterpret_cast<const float4*>(zbase)[l];
        float4 y;
        y.x = o4.x * r * nw.x * silu_f(z4.x);
        y.y = o4.y * r * nw.y * silu_f(z4.y);
        y.z = o4.z * r * nw.z * silu_f(z4.z);
        y.w = o4.w * r * nw.w * silu_f(z4.w);
        reinterpret_cast<float4*>(obase)[l] = y;
    }
}

// ---------------------------------------------------------------------------
// Launch
// ---------------------------------------------------------------------------
extern "C" void kernel_launch(void* const* d_in, const int* in_sizes, int n_in,
                              void* d_out, int out_size) {
    const float* H     = (const float*)d_in[0];
    const float* Wqkv  = (const float*)d_in[1];
    const float* Wz    = (const float*)d_in[2];
    const float* Wb    = (const float*)d_in[3];
    const float* Wa    = (const float*)d_in[4];
    const float* convw = (const float*)d_in[5];
    const float* dtb   = (const float*)d_in[6];
    const float* Alog  = (const float*)d_in[7];
    const float* normw = (const float*)d_in[8];
    const float* Wout  = (const float*)d_in[9];
    float* out = (float*)d_out;

    float *mixed, *z, *braw, *araw, *o;
    cudaGetSymbolAddress((void**)&mixed, g_mixed);
    cudaGetSymbolAddress((void**)&z,     g_z);
    cudaGetSymbolAddress((void**)&braw,  g_braw);
    cudaGetSymbolAddress((void**)&araw,  g_araw);
    cudaGetSymbolAddress((void**)&o,     g_o);

    // Projections (tensor cores, bf16-split = fp32-accurate)
    mma_gemm_nt<<<dim3(QKV_DIM / BN, T_TOKENS / BM), 256>>>(H, Wqkv, mixed, T_TOKENS, QKV_DIM, HIDDEN);
    mma_gemm_nt<<<dim3(VALUE_DIM / BN, T_TOKENS / BM), 256>>>(H, Wz, z, T_TOKENS, VALUE_DIM, HIDDEN);
    mma_gemm_nt<<<dim3(1, T_TOKENS / BM), 256>>>(H, Wb, braw, T_TOKENS, NUM_V_HEADS, HIDDEN);
    mma_gemm_nt<<<dim3(1, T_TOKENS / BM), 256>>>(H, Wa, araw, T_TOKENS, NUM_V_HEADS, HIDDEN);

    // Conv + SiLU
    conv_silu_kernel<<<dim3(QKV_DIM / 256, T_TOKENS), 256>>>(convw);

    // beta / exp(g)
    prep_ba_kernel<<<(T_TOKENS * NUM_V_HEADS + 255) / 256, 256>>>(dtb, Alog);

    // l2 norm of q,k (in place)
    l2norm_qk_kernel<<<T_TOKENS, 128>>>();

    // Gated delta rule recurrence
    recurrence_kernel<<<NUM_V_HEADS * 4, 128>>>();

    // Gated RMSNorm (in place into g_o)
    gated_norm_kernel<<<T_TOKENS, 128>>>(normw);

    // Output projection
    mma_gemm_nt<<<dim3(HIDDEN / BN, T_TOKENS / BM), 256>>>(o, Wout, out, T_TOKENS, HIDDEN, VALUE_DIM);
}